// round 17
// baseline (speedup 1.0000x reference)
#include <cuda_runtime.h>
#include <cuda_fp16.h>
#include <math.h>
#include <stdint.h>

#define BB    4
#define HH    32
#define KVH   8
#define DD    128
#define HID   4096
#define SC    8191
#define SS    8192
#define WW    512
#define BLK   16
#define NSEL  64
#define MAXBL 80
#define KSPL  16
#define NCOL  (HID + 1024 + 1024)

// ---------------- device scratch ----------------
__device__ float g_part [KSPL * BB * NCOL];
__device__ float g_q    [BB * HH * DD];
__device__ float g_kn   [BB * KVH * DD];
__device__ float g_vn   [BB * KVH * DD];
__device__ float g_tsp  [BB * HH * WW];
__device__ int   g_blist[BB * HH * MAXBL];
__device__ int   g_bcnt [BB * HH];
__device__ float g_am   [2 * BB * HH];             // attn partial max
__device__ float g_al   [2 * BB * HH];             // attn partial sumexp
__device__ float g_av   [2 * BB * HH * DD];        // attn partial weighted V
__device__ float g_ctx  [BB * HID];
__device__ float g_opart[KSPL * BB * HID];
__device__ float g_sink [4];
__device__ unsigned short g_Bt[2 * 9 * 32 * 16];   // fp16 limbs of 64*w

// ================= warp-mma helpers =================
__device__ __forceinline__ uint32_t smem_u32(const void* p) {
    uint32_t a;
    asm("{ .reg .u64 t; cvta.to.shared.u64 t, %1; cvt.u32.u64 %0, t; }" : "=r"(a) : "l"(p));
    return a;
}
#define LDSM_X4(r0, r1, r2, r3, addr) \
    asm volatile("ldmatrix.sync.aligned.m8n8.x4.shared.b16 {%0,%1,%2,%3}, [%4];" \
        : "=r"(r0), "=r"(r1), "=r"(r2), "=r"(r3) : "r"(addr))
#define LDSM_X2(r0, r1, addr) \
    asm volatile("ldmatrix.sync.aligned.m8n8.x2.shared.b16 {%0,%1}, [%2];" \
        : "=r"(r0), "=r"(r1) : "r"(addr))
#define MMA16816(d, a0, a1, a2, a3, b0, b1) \
    asm volatile("mma.sync.aligned.m16n8k16.row.col.f32.f16.f16.f32 " \
        "{%0,%1,%2,%3}, {%4,%5,%6,%7}, {%8,%9}, {%0,%1,%2,%3};" \
        : "+f"((d)[0]), "+f"((d)[1]), "+f"((d)[2]), "+f"((d)[3]) \
        : "r"(a0), "r"(a1), "r"(a2), "r"(a3), "r"(b0), "r"(b1))

#define A_PLANE_HALF 3120
#define A_SLOT_B     12480

// ================= QKV GEMV =================
__global__ void k_qkv(const float* __restrict__ hid, const float* __restrict__ Wq,
                      const float* __restrict__ Wk, const float* __restrict__ Wv) {
    __shared__ float hs[BB][256];
    const int ks = blockIdx.y, k0 = ks * 256;
    for (int i = threadIdx.x; i < BB * 256; i += 256) {
        int b = i >> 8, kk = i & 255;
        hs[b][kk] = hid[b * HID + k0 + kk];
    }
    __syncthreads();
    const int c = blockIdx.x * 256 + threadIdx.x;
    const float* Wm; int ld, cc;
    if (c < HID)              { Wm = Wq; ld = HID;  cc = c; }
    else if (c < HID + 1024)  { Wm = Wk; ld = 1024; cc = c - HID; }
    else                      { Wm = Wv; ld = 1024; cc = c - HID - 1024; }
    float a0 = 0.f, a1 = 0.f, a2 = 0.f, a3 = 0.f;
    const float* p = Wm + (size_t)k0 * ld + cc;
#pragma unroll 8
    for (int kk = 0; kk < 256; ++kk) {
        float w = p[(size_t)kk * ld];
        a0 = fmaf(hs[0][kk], w, a0);
        a1 = fmaf(hs[1][kk], w, a1);
        a2 = fmaf(hs[2][kk], w, a2);
        a3 = fmaf(hs[3][kk], w, a3);
    }
    g_part[((ks * BB + 0) * NCOL) + c] = a0;
    g_part[((ks * BB + 1) * NCOL) + c] = a1;
    g_part[((ks * BB + 2) * NCOL) + c] = a2;
    g_part[((ks * BB + 3) * NCOL) + c] = a3;
}

// ================= reduce + RoPE =================
__global__ void k_rope(const float* __restrict__ cosb, const float* __restrict__ sinb) {
    int i = blockIdx.x * 256 + threadIdx.x;
    if (i >= BB * NCOL) return;
    int b = i / NCOL, c = i - b * NCOL;
    float v = 0.f;
#pragma unroll
    for (int ks = 0; ks < KSPL; ++ks) v += g_part[(ks * BB + b) * NCOL + c];
    if (c < HID + 1024) {
        int d = c & (DD - 1);
        int pair = (d < DD / 2) ? c + DD / 2 : c - DD / 2;
        float pv = 0.f;
#pragma unroll
        for (int ks = 0; ks < KSPL; ++ks) pv += g_part[(ks * BB + b) * NCOL + pair];
        float cs = cosb[b * DD + d], sn = sinb[b * DD + d];
        float rot = (d < DD / 2) ? -pv : pv;
        float out = v * cs + rot * sn;
        if (c < HID) g_q[b * HID + c] = out;
        else         g_kn[b * (KVH * DD) + (c - HID)] = out;
    } else {
        g_vn[b * (KVH * DD) + (c - HID - 1024)] = v;
    }
}

// ====== conv2 weight prep ======
__global__ void k_prep(const float* __restrict__ c2w) {
    int idx = blockIdx.x * 256 + threadIdx.x;
    if (idx >= 4608) return;
    int c2 = idx / 144, rem = idx - c2 * 144;
    int c1 = rem / 9, t = rem - c1 * 9;
    float a = c2w[idx] * 64.f;
    __half h = __float2half(a);
    __half l = __float2half(a - __half2float(h));
    g_Bt[((0 * 9 + t) * 32 + c2) * 16 + c1] = __half_as_ushort(h);
    g_Bt[((1 * 9 + t) * 32 + c2) * 16 + c1] = __half_as_ushort(l);
}

// ================= Wo L2 prefetch (default stream, hidden under conv2) ========
__global__ void k_pf(const float4* __restrict__ W) {
    float s = 0.f;
    const size_t total = (size_t)HID * HID / 4;
    for (size_t i = (size_t)blockIdx.x * 256 + threadIdx.x; i < total;
         i += (size_t)gridDim.x * 256) {
        float4 v = __ldg(W + i);
        s += v.x + v.y + v.z + v.w;
    }
    if (s == 1.2345678e38f) g_sink[0] = s;   // never true; defeats DCE
}

// ================= mma.sync conv2 (R13/R15-proven) =================
#define CONV2_SMEM 55808

__device__ __forceinline__ void build_row(
    int hb, int W0, int tid,
    const float* xs, const float* w1s, const float* b1s, __half* As)
{
    if (hb >= 64) return;
    __half* dst0 = As + (hb & 1) * 6240;
    const float* xr0 = xs + ((hb - 1) & 3) * 132;
    const float* xr1 = xs + ( hb      & 3) * 132;
    const float* xr2 = xs + ((hb + 1) & 3) * 132;
    for (int u = tid; u < 260; u += 256) {
        int wi  = (u < 130) ? u : (u - 130);
        int c1b = (u < 130) ? 0 : 8;
        bool valid = ((unsigned)(W0 - 1 + wi) < 512u);
        float xv[9];
        xv[0] = xr0[wi]; xv[1] = xr0[wi + 1]; xv[2] = xr0[wi + 2];
        xv[3] = xr1[wi]; xv[4] = xr1[wi + 1]; xv[5] = xr1[wi + 2];
        xv[6] = xr2[wi]; xv[7] = xr2[wi + 1]; xv[8] = xr2[wi + 2];
        uint32_t oh[4], ol[4];
#pragma unroll
        for (int k = 0; k < 8; ++k) {
            int c1 = c1b + k;
            const float* wp = w1s + c1 * 12;
            float s = b1s[c1];
#pragma unroll
            for (int q = 0; q < 9; ++q) s = fmaf(wp[q], xv[q], s);
            float vv = valid ? fmaxf(s, 0.f) : 0.f;
            __half hv = __float2half(vv);
            __half lv = __float2half(vv - __half2float(hv));
            uint32_t hb_ = (uint32_t)__half_as_ushort(hv);
            uint32_t lb_ = (uint32_t)__half_as_ushort(lv);
            if (k & 1) { oh[k >> 1] |= hb_ << 16; ol[k >> 1] |= lb_ << 16; }
            else       { oh[k >> 1]  = hb_;       ol[k >> 1]  = lb_; }
        }
        __half* d = dst0 + wi * 24 + c1b;
        *(uint4*)d = make_uint4(oh[0], oh[1], oh[2], oh[3]);
        *(uint4*)(d + A_PLANE_HALF) = make_uint4(ol[0], ol[1], ol[2], ol[3]);
    }
}

__device__ __forceinline__ void epi_slot(float (&Ds)[2][2][4], float (&racc)[4],
                                         const float (&b2r)[2][2], const float (&c3r)[2][2]) {
#pragma unroll
    for (int mt = 0; mt < 2; ++mt)
#pragma unroll
        for (int ntl = 0; ntl < 2; ++ntl)
#pragma unroll
            for (int i = 0; i < 4; ++i) {
                float d = Ds[mt][ntl][i] * 0.015625f + b2r[ntl][i & 1];
                racc[mt * 2 + (i >> 1)] += fmaxf(d, 0.f) * c3r[ntl][i & 1];
                Ds[mt][ntl][i] = 0.f;
            }
}

template<int TN, int TC, int TP>
__device__ __forceinline__ void conv_step(int r,
    float (&D)[3][2][2][4], float (&racc)[4],
    uint32_t Ab, uint32_t Bb,
    const uint32_t (&bH0)[18], const uint32_t (&bH1)[18],
    int wm, int wn, uint32_t arow, uint32_t blo,
    const float (&b2r)[2][2], const float (&c3r)[2][2],
    int W0, int tid, const float* __restrict__ xim,
    float* xs, const float* w1s, const float* b1s, __half* As)
{
    const int hh = r + 3;
    const bool haspf = (tid < 132);
    float pfv = 0.f;
    if (haspf) {
        int w = W0 - 2 + tid;
        if (hh < 64 && (unsigned)w < 512u) pfv = __ldg(xim + hh * WW + w);
    }

    const uint32_t pH = Ab + (uint32_t)((r & 1) * A_SLOT_B);
#pragma unroll
    for (int dw = 0; dw < 3; ++dw) {
        uint32_t ah[2][4], al[2][4];
#pragma unroll
        for (int mt = 0; mt < 2; ++mt) {
            uint32_t ra = pH + (uint32_t)((wm * 32 + mt * 16 + dw) * 48) + arow;
            LDSM_X4(ah[mt][0], ah[mt][1], ah[mt][2], ah[mt][3], ra);
            LDSM_X4(al[mt][0], al[mt][1], al[mt][2], al[mt][3], ra + 6240);
        }
#pragma unroll
        for (int dh = 0; dh < 3; ++dh) {
            const int sl = (dh == 0) ? TN : (dh == 1 ? TC : TP);
            int h = r + 1 - dh;
            if ((unsigned)h < 64u) {
                const int t9 = dh * 3 + dw, j = t9 * 2;
                uint32_t bl0[2], bl1[2];
#pragma unroll
                for (int ntl = 0; ntl < 2; ++ntl)
                    LDSM_X2(bl0[ntl], bl1[ntl],
                            Bb + (uint32_t)(((9 + t9) * 4 + wn * 2 + ntl) * 384) + blo);
#pragma unroll
                for (int mt = 0; mt < 2; ++mt)
#pragma unroll
                    for (int ntl = 0; ntl < 2; ++ntl) {
                        MMA16816(D[sl][mt][ntl], ah[mt][0], ah[mt][1], ah[mt][2], ah[mt][3],
                                 bH0[j + ntl], bH1[j + ntl]);
                        MMA16816(D[sl][mt][ntl], al[mt][0], al[mt][1], al[mt][2], al[mt][3],
                                 bH0[j + ntl], bH1[j + ntl]);
                        MMA16816(D[sl][mt][ntl], ah[mt][0], ah[mt][1], ah[mt][2], ah[mt][3],
                                 bl0[ntl], bl1[ntl]);
                    }
            }
        }
    }
    if (r >= 1) epi_slot(D[TP], racc, b2r, c3r);
    if (haspf) xs[((r + 3) & 3) * 132 + tid] = pfv;
    build_row(r + 1, W0, tid, xs, w1s, b1s, As);
    __syncthreads();
}

__global__ void __launch_bounds__(256, 2)
k_conv2(const float* __restrict__ hist,
        const float* __restrict__ c1w, const float* __restrict__ c1b,
        const float* __restrict__ c2b, const float* __restrict__ c3w,
        const float* __restrict__ c3b) {
    extern __shared__ __align__(16) unsigned char smraw[];
    __half* As = (__half*)smraw;
    __half* Bs = As + 12480;
    float*  xs = (float*)(Bs + 13824);
    float* w1s = xs + 528;
    float* b1s = w1s + 192;
    float* b2s = b1s + 16;
    float* c3s = b2s + 32;
    __shared__ float redp[8][32];

    const int n   = blockIdx.y;
    const int W0  = blockIdx.x * 128;
    const int tid = threadIdx.x;
    const int lane = tid & 31, wid = tid >> 5;
    const int wm = wid >> 1, wn = wid & 1;

    for (int i = tid; i < 192; i += 256)
        w1s[i] = ((i % 12) < 9) ? c1w[(i / 12) * 9 + (i % 12)] : 0.f;
    if (tid < 16) b1s[tid] = c1b[tid];
    if (tid < 32) { b2s[tid] = c2b[tid]; c3s[tid] = c3w[tid]; }
    for (int i = tid; i < 2 * 9 * 32 * 16; i += 256) {
        int k = i & 15, c2 = (i >> 4) & 31, t = i >> 9;
        Bs[(t * 4 + (c2 >> 3)) * 192 + (c2 & 7) * 24 + k] = __ushort_as_half(g_Bt[i]);
    }

    const float* xim = hist + (size_t)n * 64 * WW;
    for (int i = tid; i < 4 * 132; i += 256) {
        int rr = i / 132, cc = i - rr * 132;
        int hh = rr - 1;
        int w = W0 - 2 + cc;
        float v = 0.f;
        if (hh >= 0 && (unsigned)w < 512u) v = xim[hh * WW + w];
        xs[(hh & 3) * 132 + cc] = v;
    }
    __syncthreads();
    build_row(0, W0, tid, xs, w1s, b1s, As);
    __syncthreads();

    const uint32_t Bb = smem_u32(Bs);
    const uint32_t blo = (uint32_t)((lane & 7) * 48 + (((lane >> 3) & 1) << 4));
    uint32_t bH0[18], bH1[18];
#pragma unroll
    for (int t = 0; t < 9; ++t)
#pragma unroll
        for (int ntl = 0; ntl < 2; ++ntl) {
            int j = t * 2 + ntl;
            LDSM_X2(bH0[j], bH1[j], Bb + (uint32_t)((t * 4 + wn * 2 + ntl) * 384) + blo);
        }

    float b2r[2][2], c3r[2][2];
#pragma unroll
    for (int ntl = 0; ntl < 2; ++ntl)
#pragma unroll
        for (int lo = 0; lo < 2; ++lo) {
            int c2 = wn * 16 + ntl * 8 + 2 * (lane & 3) + lo;
            b2r[ntl][lo] = b2s[c2];
            c3r[ntl][lo] = c3s[c2];
        }

    const uint32_t Ab = smem_u32(As);
    const uint32_t arow = (uint32_t)((lane & 15) * 48 + ((lane >> 4) << 4));

    float D[3][2][2][4];
#pragma unroll
    for (int s = 0; s < 3; ++s)
#pragma unroll
        for (int mt = 0; mt < 2; ++mt)
#pragma unroll
            for (int ntl = 0; ntl < 2; ++ntl)
#pragma unroll
                for (int i = 0; i < 4; ++i) D[s][mt][ntl][i] = 0.f;
    float racc[4] = {0.f, 0.f, 0.f, 0.f};

    for (int rb = 0; rb < 63; rb += 3) {
        conv_step<1, 0, 2>(rb + 0, D, racc, Ab, Bb, bH0, bH1, wm, wn, arow, blo,
                           b2r, c3r, W0, tid, xim, xs, w1s, b1s, As);
        conv_step<2, 1, 0>(rb + 1, D, racc, Ab, Bb, bH0, bH1, wm, wn, arow, blo,
                           b2r, c3r, W0, tid, xim, xs, w1s, b1s, As);
        conv_step<0, 2, 1>(rb + 2, D, racc, Ab, Bb, bH0, bH1, wm, wn, arow, blo,
                           b2r, c3r, W0, tid, xim, xs, w1s, b1s, As);
    }
    conv_step<1, 0, 2>(63, D, racc, Ab, Bb, bH0, bH1, wm, wn, arow, blo,
                       b2r, c3r, W0, tid, xim, xs, w1s, b1s, As);
    epi_slot(D[0], racc, b2r, c3r);     // h = 63

#pragma unroll
    for (int j = 0; j < 4; ++j) {
        racc[j] += __shfl_xor_sync(0xffffffffu, racc[j], 1);
        racc[j] += __shfl_xor_sync(0xffffffffu, racc[j], 2);
    }
    if ((lane & 3) == 0) {
        int q = lane >> 2;
#pragma unroll
        for (int j = 0; j < 4; ++j) redp[wid][j * 8 + q] = racc[j];
    }
    __syncthreads();

    if (tid < 128) {
        int wm2 = tid >> 5, idx = tid & 31;
        int j = idx >> 3, q = idx & 7;
        float s = redp[wm2 * 2 + 0][idx] + redp[wm2 * 2 + 1][idx];
        int w = W0 + wm2 * 32 + (j >> 1) * 16 + ((j & 1) << 3) + q;
        g_tsp[n * WW + w] = s * (1.f / 64.f) + c3b[0];
    }
}

// ================= top-k via exact rank count + forced sink/local =============
__global__ void k_topk() {
    const int bh = blockIdx.x;
    __shared__ float v[WW];
    __shared__ unsigned char sel[WW];
    const int tid = threadIdx.x;

    for (int i = tid; i < WW; i += 256) v[i] = g_tsp[bh * WW + i];
    __syncthreads();

    for (int e = tid; e < WW; e += 256) {
        const float ve = v[e];
        int cnt = 0;
#pragma unroll 8
        for (int j = 0; j < WW; ++j) {
            float vj = v[j];
            cnt += (vj > ve || (vj == ve && j < e)) ? 1 : 0;
        }
        sel[e] = (cnt < NSEL) ? 1 : 0;
    }
    __syncthreads();
    if (tid == 0) {
        for (int i = 0; i < 4; ++i) { sel[i] = 1; sel[WW - 4 + i] = 1; }
        int cnt = 0;
        for (int w = 0; w < WW; ++w)
            if (sel[w]) g_blist[bh * MAXBL + (cnt++)] = w;
        g_bcnt[bh] = cnt;
    }
}

// ============ sparse attention, split-KV: grid (128, 2), 512 threads ==========
__global__ void k_attn_p(const float* __restrict__ kc, const float* __restrict__ vc) {
    const int bh = blockIdx.x;
    const int half = blockIdx.y;
    const int b = bh >> 5, h = bh & 31, kvh = h >> 2;
    const int tid = threadIdx.x;
    __shared__ float qs[DD];
    __shared__ float sc[(MAXBL / 2 + 1) * BLK];
    __shared__ float redf[512];
    __shared__ float vacc[16][DD];

    const int cnt = g_bcnt[bh];
    const int blo_ = (cnt * half) >> 1;
    const int bhi_ = (cnt * (half + 1)) >> 1;
    const int ntok = (bhi_ - blo_) * BLK;
    if (tid < DD) qs[tid] = g_q[(b * HH + h) * DD + tid];
    __syncthreads();

    const int wid = tid >> 5, lane = tid & 31;
    const float iscale = 0.08838834764831845f;
    const float4 q4 = *(const float4*)(qs + lane * 4);
    const size_t kvbase = (size_t)(b * KVH + kvh) * SC;

    for (int t = wid; t < ntok; t += 16) {
        int blk = g_blist[bh * MAXBL + blo_ + (t >> 4)];
        int s = blk * BLK + (t & 15);
        const float* kr = (s == SS - 1) ? (g_kn + (b * KVH + kvh) * DD)
                                        : (kc + (kvbase + s) * DD);
        float4 k4 = ((const float4*)kr)[lane];
        float sum = fmaf(q4.x, k4.x, fmaf(q4.y, k4.y, fmaf(q4.z, k4.z, q4.w * k4.w)));
#pragma unroll
        for (int o = 16; o > 0; o >>= 1) sum += __shfl_xor_sync(0xffffffffu, sum, o);
        if (lane == 0) sc[t] = sum * iscale;
    }
    __syncthreads();

    float m = -3.0e38f;
    for (int t = tid; t < ntok; t += 512) m = fmaxf(m, sc[t]);
    redf[tid] = m; __syncthreads();
    for (int st = 256; st > 0; st >>= 1) {
        if (tid < st) redf[tid] = fmaxf(redf[tid], redf[tid + st]);
        __syncthreads();
    }
    m = redf[0];
    __syncthreads();

    float lp = 0.f;
    for (int t = tid; t < ntok; t += 512) { float p = expf(sc[t] - m); sc[t] = p; lp += p; }
    redf[tid] = lp; __syncthreads();
    for (int st = 256; st > 0; st >>= 1) {
        if (tid < st) redf[tid] += redf[tid + st];
        __syncthreads();
    }
    const float lsum = redf[0];
    __syncthreads();

    float4 a4 = make_float4(0.f, 0.f, 0.f, 0.f);
    for (int t = wid; t < ntok; t += 16) {
        int blk = g_blist[bh * MAXBL + blo_ + (t >> 4)];
        int s = blk * BLK + (t & 15);
        const float* vr = (s == SS - 1) ? (g_vn + (b * KVH + kvh) * DD)
                                        : (vc + (kvbase + s) * DD);
        float4 v4 = ((const float4*)vr)[lane];
        float p = sc[t];
        a4.x = fmaf(p, v4.x, a4.x);
        a4.y = fmaf(p, v4.y, a4.y);
        a4.z = fmaf(p, v4.z, a4.z);
        a4.w = fmaf(p, v4.w, a4.w);
    }
    *(float4*)(&vacc[wid][lane * 4]) = a4;
    __syncthreads();

    const int slot = half * (BB * HH) + bh;
    if (tid < DD) {
        float s = 0.f;
#pragma unroll
        for (int g = 0; g < 16; ++g) s += vacc[g][tid];
        g_av[slot * DD + tid] = s;
    }
    if (tid == 0) { g_am[slot] = m; g_al[slot] = lsum; }
}

// combine the two softmax partials (fixed order, deterministic)
__global__ void k_attn_c() {
    const int bh = blockIdx.x;
    const int tid = threadIdx.x;        // 128
    const int b = bh >> 5, h = bh & 31;
    float m0 = g_am[bh], m1 = g_am[BB * HH + bh];
    float m = fmaxf(m0, m1);
    float w0 = expf(m0 - m), w1 = expf(m1 - m);
    float l = g_al[bh] * w0 + g_al[BB * HH + bh] * w1;
    float v = g_av[bh * DD + tid] * w0 + g_av[(BB * HH + bh) * DD + tid] * w1;
    g_ctx[b * HID + h * DD + tid] = v / l;
}

// ================= Wo GEMV =================
__global__ void k_out(const float* __restrict__ Wo) {
    __shared__ float cs[BB][256];
    const int ks = blockIdx.y, k0 = ks * 256;
    for (int i = threadIdx.x; i < BB * 256; i += 256) {
        int b = i >> 8, kk = i & 255;
        cs[b][kk] = g_ctx[b * HID + k0 + kk];
    }
    __syncthreads();
    const int c = blockIdx.x * 256 + threadIdx.x;
    float a0 = 0.f, a1 = 0.f, a2 = 0.f, a3 = 0.f;
    const float* p = Wo + (size_t)k0 * HID + c;
#pragma unroll 8
    for (int kk = 0; kk < 256; ++kk) {
        float w = p[(size_t)kk * HID];
        a0 = fmaf(cs[0][kk], w, a0);
        a1 = fmaf(cs[1][kk], w, a1);
        a2 = fmaf(cs[2][kk], w, a2);
        a3 = fmaf(cs[3][kk], w, a3);
    }
    g_opart[(ks * BB + 0) * HID + c] = a0;
    g_opart[(ks * BB + 1) * HID + c] = a1;
    g_opart[(ks * BB + 2) * HID + c] = a2;
    g_opart[(ks * BB + 3) * HID + c] = a3;
}

__global__ void k_red_out(float* __restrict__ out) {
    int i = blockIdx.x * 256 + threadIdx.x;
    if (i >= BB * HID) return;
    int b = i / HID, c = i - b * HID;
    float s = 0.f;
#pragma unroll
    for (int ks = 0; ks < KSPL; ++ks) s += g_opart[(ks * BB + b) * HID + c];
    out[i] = s;
}

// ================= host launcher (forked graph, 2 streams as in R15) ==========
extern "C" void kernel_launch(void* const* d_in, const int* in_sizes, int n_in,
                              void* d_out, int out_size) {
    const float* hid  = (const float*)d_in[0];
    const float* kc   = (const float*)d_in[1];
    const float* vc   = (const float*)d_in[2];
    const float* hist = (const float*)d_in[3];
    const float* cosb = (const float*)d_in[4];
    const float* sinb = (const float*)d_in[5];
    const float* Wq   = (const float*)d_in[6];
    const float* Wk   = (const float*)d_in[7];
    const float* Wv   = (const float*)d_in[8];
    const float* Wo   = (const float*)d_in[9];
    const float* c1w  = (const float*)d_in[10];
    const float* c1b  = (const float*)d_in[11];
    const float* c2w  = (const float*)d_in[12];
    const float* c2b  = (const float*)d_in[13];
    const float* c3w  = (const float*)d_in[14];
    const float* c3b  = (const float*)d_in[15];
    float* out = (float*)d_out;

    cudaFuncSetAttribute(k_conv2, cudaFuncAttributeMaxDynamicSharedMemorySize, CONV2_SMEM);

    cudaStream_t s2;
    cudaEvent_t e0, e1;
    cudaStreamCreateWithFlags(&s2, cudaStreamNonBlocking);
    cudaEventCreateWithFlags(&e0, cudaEventDisableTiming);
    cudaEventCreateWithFlags(&e1, cudaEventDisableTiming);

    cudaEventRecord(e0, 0);
    cudaStreamWaitEvent(s2, e0, 0);

    // branch A (s2): conv pipeline
    k_prep <<<18, 256, 0, s2>>>(c2w);
    k_conv2<<<dim3(4, BB * HH), 256, CONV2_SMEM, s2>>>(hist, c1w, c1b, c2b, c3w, c3b);
    k_topk <<<BB * HH, 256, 0, s2>>>();
    cudaEventRecord(e1, s2);

    // branch B (default): qkv + rope + Wo L2 prefetch (all hidden under conv2)
    k_qkv <<<dim3(NCOL / 256, KSPL), 256>>>(hid, Wq, Wk, Wv);
    k_rope<<<(BB * NCOL + 255) / 256, 256>>>(cosb, sinb);
    k_pf  <<<1024, 256>>>((const float4*)Wo);

    // join, then tail
    cudaStreamWaitEvent(0, e1, 0);
    k_attn_p <<<dim3(BB * HH, 2), 512>>>(kc, vc);
    k_attn_c <<<BB * HH, 128>>>();
    k_out    <<<dim3(HID / 256, KSPL), 256>>>(Wo);
    k_red_out<<<(BB * HID + 255) / 256, 256>>>(out);
    // NOTE: stream/events intentionally not destroyed — destroying a stream
    // participating in an active capture invalidates the capture; handles
    // leak only across the harness's bounded number of launch calls.
}